// round 4
// baseline (speedup 1.0000x reference)
#include <cuda_runtime.h>
#include <cuda_bf16.h>
#include <stdint.h>

// Canny NMS, collapsed conv form, direct-gmem with lane-stride-1 mapping.
// idx = floor(ori/45)&7; (dy,dx) from packed table;
//   pos = m + bias[idx]   - m[y+dy, x+dx]   (0 outside image: SAME padding)
//   neg = m + bias[idx^4] - m[y-dy, x-dx]
//   out = (min(pos,neg) > 0) ? m : 0
//
// Warp covers a 128-pixel strip; thread's 4 pixels are 32 apart so every
// load instruction has stride-1 lane addressing (minimal L1 wavefronts).

#define IMG_H 4096
#define IMG_W 4096

// dx per idx: {1,1,0,-1,-1,-1,0,1} -> (dx+1) 2-bit packed
// dy per idx: {0,1,1,1,0,-1,-1,-1} -> (dy+1) 2-bit packed
#define DX_PACK 36890u
#define DY_PACK 425u

__global__ __launch_bounds__(256) void nms_kernel(
    const float* __restrict__ mag,
    const float* __restrict__ ori,
    const float* __restrict__ bias,
    float* __restrict__ out)
{
    __shared__ float sbias[8];
    const int lane = threadIdx.x;                 // 0..31
    const int tid  = threadIdx.y * 32 + lane;
    if (tid < 8) sbias[tid] = bias[tid];
    __syncthreads();

    const int y     = blockIdx.y * 8 + threadIdx.y;
    const int xbase = blockIdx.x * 128 + lane;
    const int rowb  = y << 12;                    // y * 4096 (32-bit math)

#pragma unroll
    for (int i = 0; i < 4; i++) {
        const int x = xbase + i * 32;
        const int g = rowb + x;

        const float m = mag[g];                   // coalesced
        const float o = __ldcs(ori + g);          // streaming, no reuse

        const int idx = ((int)(o * (1.0f / 45.0f))) & 7;
        const int sh  = idx << 1;
        const int dx  = (int)((DX_PACK >> sh) & 3u) - 1;
        const int dy  = (int)((DY_PACK >> sh) & 3u) - 1;

        // forward neighbor (stride-1 lane addresses, <=6 lines per warp instr)
        const int ny = y + dy, nx = x + dx;
        float np = 0.0f;
        if ((unsigned)ny < (unsigned)IMG_H && (unsigned)nx < (unsigned)IMG_W)
            np = __ldg(mag + (ny << 12) + nx);

        // backward neighbor
        const int my = y - dy, mx = x - dx;
        float nn = 0.0f;
        if ((unsigned)my < (unsigned)IMG_H && (unsigned)mx < (unsigned)IMG_W)
            nn = __ldg(mag + (my << 12) + mx);

        const float pos = m + sbias[idx]     - np;   // conflict-free LDS (8 banks)
        const float neg = m + sbias[idx ^ 4] - nn;
        const float r   = (fminf(pos, neg) > 0.0f) ? m : 0.0f;

        __stcs(out + g, r);                       // streaming store
    }
}

extern "C" void kernel_launch(void* const* d_in, const int* in_sizes, int n_in,
                              void* d_out, int out_size)
{
    const float* mag  = (const float*)d_in[0];   // grad_magnitude [1,1,4096,4096]
    const float* ori  = (const float*)d_in[1];   // grad_orientation
    // d_in[2] = weight [8,1,3,3] -- fixed directional filters, collapsed analytically
    const float* bias = (const float*)d_in[3];   // bias [8]
    float* out = (float*)d_out;

    dim3 block(32, 8);                            // 128 x 8 pixel tile per block
    dim3 grid(IMG_W / 128, IMG_H / 8);            // (32, 512)
    nms_kernel<<<grid, block>>>(mag, ori, bias, out);
}

// round 5
// speedup vs baseline: 1.4234x; 1.4234x over previous
#include <cuda_runtime.h>
#include <cuda_bf16.h>
#include <stdint.h>

// Canny NMS, collapsed conv form.
// smem zero-halo tile (coalesced float4 fill) + lane-stride-1 compute mapping
// so every scattered LDS has consecutive lane addresses (conflict degree <=2).
// idx = floor(ori/45)&7; off = dy*TW+dx;
//   pos = m + bias[idx]   - tile[p+off]
//   neg = m + bias[idx^4] - tile[p-off]
//   out = (min(pos,neg) > 0) ? m : 0     (zero halo == SAME padding)

#define IMG_H 4096
#define IMG_W 4096
#define TW 136           // 128 + 4-float halo each side (float4-aligned fill)
#define TH 10            // 8 rows + 1 halo row each side

// dx per idx: {1,1,0,-1,-1,-1,0,1} -> (dx+1) 2-bit packed
// dy per idx: {0,1,1,1,0,-1,-1,-1} -> (dy+1) 2-bit packed
#define DX_PACK 36890u
#define DY_PACK 425u

__global__ __launch_bounds__(256) void nms_kernel(
    const float* __restrict__ mag,
    const float* __restrict__ ori,
    const float* __restrict__ bias,
    float* __restrict__ out)
{
    __shared__ float tile[TH * TW];    // 5440 B
    __shared__ float sbias[8];

    const int lane = threadIdx.x;                  // 0..31
    const int tid  = threadIdx.y * 32 + lane;      // 0..255

    if (tid < 8) sbias[tid] = bias[tid];

    // ---- cooperative fill: 34 float4 x 10 rows = 340 float4, coalesced ----
    const int gx0 = blockIdx.x * 128 - 4;          // float4 aligned
    const int gy0 = blockIdx.y * 8 - 1;
#pragma unroll
    for (int e = tid; e < 340; e += 256) {
        const int row = e / 34;
        const int c4  = e - row * 34;
        const int gx  = gx0 + c4 * 4;              // all-in or all-out per float4
        const int gy  = gy0 + row;
        float4 v = make_float4(0.f, 0.f, 0.f, 0.f);
        if ((unsigned)gy < (unsigned)IMG_H && (unsigned)gx < (unsigned)IMG_W)
            v = *reinterpret_cast<const float4*>(mag + (gy << 12) + gx);
        *reinterpret_cast<float4*>(&tile[row * TW + c4 * 4]) = v;
    }
    __syncthreads();

    // ---- compute: 4 pixels per thread, lane-stride-1 (x = base + i*32 + lane) ----
    const int y     = blockIdx.y * 8 + threadIdx.y;
    const int xb    = blockIdx.x * 128 + lane;
    const int rowb  = y << 12;
    const int prow  = (threadIdx.y + 1) * TW + 4 + lane;

    // front-load the 4 orientation values (independent, coalesced, streaming)
    float O[4];
#pragma unroll
    for (int i = 0; i < 4; i++) O[i] = __ldcs(ori + rowb + xb + i * 32);

#pragma unroll
    for (int i = 0; i < 4; i++) {
        const int p   = prow + i * 32;
        const int idx = ((int)(O[i] * (1.0f / 45.0f))) & 7;
        const int sh  = idx << 1;
        const int dx  = (int)((DX_PACK >> sh) & 3u) - 1;
        const int dy  = (int)((DY_PACK >> sh) & 3u) - 1;
        const int off = dy * TW + dx;

        const float m  = tile[p];                  // stride-1, conflict-free
        const float np = tile[p + off];            // stride-1 +/-1 jitter
        const float nn = tile[p - off];

        const float pos = m + sbias[idx]     - np;
        const float neg = m + sbias[idx ^ 4] - nn;
        const float r   = (fminf(pos, neg) > 0.0f) ? m : 0.0f;

        __stcs(out + rowb + xb + i * 32, r);       // coalesced streaming store
    }
}

extern "C" void kernel_launch(void* const* d_in, const int* in_sizes, int n_in,
                              void* d_out, int out_size)
{
    const float* mag  = (const float*)d_in[0];   // grad_magnitude [1,1,4096,4096]
    const float* ori  = (const float*)d_in[1];   // grad_orientation
    // d_in[2] = weight [8,1,3,3] -- fixed directional filters, collapsed analytically
    const float* bias = (const float*)d_in[3];   // bias [8]
    float* out = (float*)d_out;

    dim3 block(32, 8);                            // 128 x 8 pixel tile per block
    dim3 grid(IMG_W / 128, IMG_H / 8);            // (32, 512)
    nms_kernel<<<grid, block>>>(mag, ori, bias, out);
}

// round 6
// speedup vs baseline: 1.4417x; 1.0129x over previous
#include <cuda_runtime.h>
#include <cuda_bf16.h>
#include <stdint.h>

// Canny NMS, collapsed conv form.
// smem zero-halo tile (16 core rows) + lane-stride-1 compute mapping,
// orientation loads issued BEFORE tile fill to maximize in-flight DRAM lines.
// idx = floor(ori/45)&7; off = dy*TW+dx;
//   pos = m + bias[idx]   - tile[p+off]
//   neg = m + bias[idx^4] - tile[p-off]
//   out = (min(pos,neg) > 0) ? m : 0     (zero halo == SAME padding)

#define IMG_H 4096
#define IMG_W 4096
#define TW 136            // 128 + 4-float halo each side (float4-aligned fill)
#define TH 18             // 16 core rows + 1 halo row each side
#define FILL_V4 (TH * 34) // 612 float4 per tile

// dx per idx: {1,1,0,-1,-1,-1,0,1} -> (dx+1) 2-bit packed
// dy per idx: {0,1,1,1,0,-1,-1,-1} -> (dy+1) 2-bit packed
#define DX_PACK 36890u
#define DY_PACK 425u

__global__ __launch_bounds__(256) void nms_kernel(
    const float* __restrict__ mag,
    const float* __restrict__ ori,
    const float* __restrict__ bias,
    float* __restrict__ out)
{
    __shared__ float tile[TH * TW];    // 9792 B
    __shared__ float sbias[8];

    const int lane = threadIdx.x;                  // 0..31
    const int wy   = threadIdx.y;                  // 0..7
    const int tid  = wy * 32 + lane;

    if (tid < 8) sbias[tid] = bias[tid];

    // ---- front-load 8 orientation values (2 rows x 4 strips per thread) ----
    // Issued before the tile fill so these DRAM lines are in flight during
    // fill + barrier. Coalesced scalar loads, streaming (no reuse).
    const int xb   = blockIdx.x * 128 + lane;
    const int y0   = blockIdx.y * 16 + 2 * wy;     // first of this thread's 2 rows
    const int g0   = (y0 << 12) + xb;              // row y0
    const int g1   = g0 + IMG_W;                   // row y0+1
    float O[8];
#pragma unroll
    for (int j = 0; j < 4; j++) {
        O[j]     = __ldcs(ori + g0 + j * 32);
        O[4 + j] = __ldcs(ori + g1 + j * 32);
    }

    // ---- cooperative tile fill: 34 float4 x 18 rows, coalesced ----
    const int gx0 = blockIdx.x * 128 - 4;          // float4 aligned
    const int gy0 = blockIdx.y * 16 - 1;
#pragma unroll
    for (int e = tid; e < FILL_V4; e += 256) {
        const int row = e / 34;
        const int c4  = e - row * 34;
        const int gx  = gx0 + c4 * 4;              // all-in or all-out per float4
        const int gy  = gy0 + row;
        float4 v = make_float4(0.f, 0.f, 0.f, 0.f);
        if ((unsigned)gy < (unsigned)IMG_H && (unsigned)gx < (unsigned)IMG_W)
            v = *reinterpret_cast<const float4*>(mag + (gy << 12) + gx);
        *reinterpret_cast<float4*>(&tile[row * TW + c4 * 4]) = v;
    }
    __syncthreads();

    // ---- compute: 8 pixels per thread, lane-stride-1 ----
    const int p0 = (2 * wy + 1) * TW + 4 + lane;   // tile idx, row y0
    float R[8];
#pragma unroll
    for (int k = 0; k < 2; k++) {
#pragma unroll
        for (int j = 0; j < 4; j++) {
            const int q   = k * 4 + j;
            const int p   = p0 + k * TW + j * 32;
            const int idx = ((int)(O[q] * (1.0f / 45.0f))) & 7;
            const int sh  = idx << 1;
            const int dx  = (int)((DX_PACK >> sh) & 3u) - 1;
            const int dy  = (int)((DY_PACK >> sh) & 3u) - 1;
            const int off = dy * TW + dx;

            const float m  = tile[p];              // stride-1, conflict-free
            const float np = tile[p + off];        // stride-1 +/-1 jitter
            const float nn = tile[p - off];

            const float pos = m + sbias[idx]     - np;
            const float neg = m + sbias[idx ^ 4] - nn;
            R[q] = (fminf(pos, neg) > 0.0f) ? m : 0.0f;
        }
    }

    // ---- coalesced streaming stores ----
#pragma unroll
    for (int j = 0; j < 4; j++) {
        __stcs(out + g0 + j * 32, R[j]);
        __stcs(out + g1 + j * 32, R[4 + j]);
    }
}

extern "C" void kernel_launch(void* const* d_in, const int* in_sizes, int n_in,
                              void* d_out, int out_size)
{
    const float* mag  = (const float*)d_in[0];   // grad_magnitude [1,1,4096,4096]
    const float* ori  = (const float*)d_in[1];   // grad_orientation
    // d_in[2] = weight [8,1,3,3] -- fixed directional filters, collapsed analytically
    const float* bias = (const float*)d_in[3];   // bias [8]
    float* out = (float*)d_out;

    dim3 block(32, 8);                            // 128 x 16 pixel tile per block
    dim3 grid(IMG_W / 128, IMG_H / 16);           // (32, 256)
    nms_kernel<<<grid, block>>>(mag, ori, bias, out);
}

// round 7
// speedup vs baseline: 1.4954x; 1.0372x over previous
#include <cuda_runtime.h>
#include <cuda_bf16.h>
#include <stdint.h>

// Canny NMS, collapsed conv form. Direct gmem, lane-stride-1, branch-free.
// idx = floor(ori/45)&7; (dy,dx) from packed table;
//   pos = m + bias[idx]   - m[y+dy, x+dx]   (0 outside: SAME padding)
//   neg = m + bias[idx^4] - m[y-dy, x-dx]
//   out = (min(pos,neg) > 0) ? m : 0
//
// Phased for load batching: all stream loads -> all scattered loads
// (unconditional, coords clamped, OOB zeroed by select) -> compute -> stores.

#define IMG_H 4096
#define IMG_W 4096

// dx per idx: {1,1,0,-1,-1,-1,0,1} -> (dx+1) 2-bit packed
// dy per idx: {0,1,1,1,0,-1,-1,-1} -> (dy+1) 2-bit packed
#define DX_PACK 36890u
#define DY_PACK 425u

__global__ __launch_bounds__(256) void nms_kernel(
    const float* __restrict__ mag,
    const float* __restrict__ ori,
    const float* __restrict__ bias,
    float* __restrict__ out)
{
    __shared__ float sbias[8];
    const int lane = threadIdx.x;                 // 0..31
    const int wy   = threadIdx.y;                 // 0..7
    const int tid  = wy * 32 + lane;
    if (tid < 8) sbias[tid] = bias[tid];
    __syncthreads();

    const int y    = blockIdx.y * 8 + wy;
    const int xb   = blockIdx.x * 128 + lane;     // lane-stride-1
    const int rowb = y << 12;

    // ---- Phase A: 8 independent stream loads (coalesced 128B/warp each) ----
    float O[4], M[4];
#pragma unroll
    for (int j = 0; j < 4; j++) {
        O[j] = __ldcs(ori + rowb + xb + j * 32);
        M[j] = __ldg (mag + rowb + xb + j * 32);
    }

    // ---- Phase B: decode + 8 unconditional scattered loads (clamped) ----
    float NP[4], NN[4];
    int   IDX[4];
#pragma unroll
    for (int j = 0; j < 4; j++) {
        const int x   = xb + j * 32;
        const int idx = ((int)(O[j] * (1.0f / 45.0f))) & 7;
        IDX[j] = idx;
        const int sh  = idx << 1;
        const int dx  = (int)((DX_PACK >> sh) & 3u) - 1;
        const int dy  = (int)((DY_PACK >> sh) & 3u) - 1;

        const int ny = y + dy, nx = x + dx;       // forward neighbor
        const int my = y - dy, mx = x - dx;       // backward neighbor
        const bool fin = ((unsigned)ny < (unsigned)IMG_H) &
                         ((unsigned)nx < (unsigned)IMG_W);
        const bool bin = ((unsigned)my < (unsigned)IMG_H) &
                         ((unsigned)mx < (unsigned)IMG_W);
        const int fa = (min(max(ny, 0), IMG_H - 1) << 12) + min(max(nx, 0), IMG_W - 1);
        const int ba = (min(max(my, 0), IMG_H - 1) << 12) + min(max(mx, 0), IMG_W - 1);

        const float fv = __ldg(mag + fa);         // always valid address
        const float bv = __ldg(mag + ba);
        NP[j] = fin ? fv : 0.0f;                  // SAME zero padding
        NN[j] = bin ? bv : 0.0f;
    }

    // ---- Phase C: compute ----
    float R[4];
#pragma unroll
    for (int j = 0; j < 4; j++) {
        const float pos = M[j] + sbias[IDX[j]]     - NP[j];
        const float neg = M[j] + sbias[IDX[j] ^ 4] - NN[j];
        R[j] = (fminf(pos, neg) > 0.0f) ? M[j] : 0.0f;
    }

    // ---- Phase D: coalesced streaming stores ----
#pragma unroll
    for (int j = 0; j < 4; j++)
        __stcs(out + rowb + xb + j * 32, R[j]);
}

extern "C" void kernel_launch(void* const* d_in, const int* in_sizes, int n_in,
                              void* d_out, int out_size)
{
    const float* mag  = (const float*)d_in[0];   // grad_magnitude [1,1,4096,4096]
    const float* ori  = (const float*)d_in[1];   // grad_orientation
    // d_in[2] = weight [8,1,3,3] -- fixed directional filters, collapsed analytically
    const float* bias = (const float*)d_in[3];   // bias [8]
    float* out = (float*)d_out;

    dim3 block(32, 8);                            // 128 x 8 pixels per block
    dim3 grid(IMG_W / 128, IMG_H / 8);            // (32, 512)
    nms_kernel<<<grid, block>>>(mag, ori, bias, out);
}

// round 8
// speedup vs baseline: 1.5928x; 1.0651x over previous
#include <cuda_runtime.h>
#include <cuda_bf16.h>
#include <stdint.h>

// Canny NMS, collapsed conv form — zero scattered loads.
// Per pixel: idx = floor(ori/45)&7. The 8 compass neighbors live in the
// register window {U,C,D} x {i,i+1,i+2}; fwd = nb[idx], bwd = nb[idx^4]
// selected via a shared 8-SEL predicate tree.
//   pos = m + bias[idx]   - fwd
//   neg = m + bias[idx^4] - bwd
//   out = (min(pos,neg) > 0) ? m : 0      (zero rows/cols = SAME padding)

#define IMG_H 4096
#define IMG_W 4096
#define FULLMASK 0xFFFFFFFFu

__global__ __launch_bounds__(256) void nms_kernel(
    const float* __restrict__ mag,
    const float* __restrict__ ori,
    const float* __restrict__ bias,
    float* __restrict__ out)
{
    __shared__ float sbias[8];
    const int lane = threadIdx.x;                   // 0..31
    const int wy   = threadIdx.y;                   // 0..7
    const int tid  = wy * 32 + lane;
    if (tid < 8) sbias[tid] = bias[tid];
    __syncthreads();

    const int x = (blockIdx.x * 32 + lane) * 4;
    const int y = blockIdx.y * 8 + wy;
    const int base = (y << 12) + x;

    const float4 z4 = make_float4(0.f, 0.f, 0.f, 0.f);

    // ---- vector loads: 3 mag rows + orientation (all coalesced 512B/warp) ----
    const float4 c4 = *reinterpret_cast<const float4*>(mag + base);
    const float4 u4 = (y > 0)         ? *reinterpret_cast<const float4*>(mag + base - IMG_W) : z4;
    const float4 d4 = (y < IMG_H - 1) ? *reinterpret_cast<const float4*>(mag + base + IMG_W) : z4;
    const float4 o4 = __ldcs(reinterpret_cast<const float4*>(ori + base));

    // ---- extend rows to 6 columns via shuffles ----
    float cl = __shfl_up_sync(FULLMASK, c4.w, 1);
    float ul = __shfl_up_sync(FULLMASK, u4.w, 1);
    float dl = __shfl_up_sync(FULLMASK, d4.w, 1);
    float cr = __shfl_down_sync(FULLMASK, c4.x, 1);
    float ur = __shfl_down_sync(FULLMASK, u4.x, 1);
    float dr = __shfl_down_sync(FULLMASK, d4.x, 1);

    // warp-edge lanes: patch from gmem (2 active lanes -> 1-2 wavefronts)
    if (lane == 0) {
        const bool ok = (x > 0);
        cl = ok ? __ldg(mag + base - 1) : 0.f;
        ul = (ok && y > 0)         ? __ldg(mag + base - IMG_W - 1) : 0.f;
        dl = (ok && y < IMG_H - 1) ? __ldg(mag + base + IMG_W - 1) : 0.f;
    } else if (lane == 31) {
        const bool ok = (x + 4 < IMG_W);
        cr = ok ? __ldg(mag + base + 4) : 0.f;
        ur = (ok && y > 0)         ? __ldg(mag + base - IMG_W + 4) : 0.f;
        dr = (ok && y < IMG_H - 1) ? __ldg(mag + base + IMG_W + 4) : 0.f;
    }

    const float U[6] = { ul, u4.x, u4.y, u4.z, u4.w, ur };
    const float C[6] = { cl, c4.x, c4.y, c4.z, c4.w, cr };
    const float D[6] = { dl, d4.x, d4.y, d4.z, d4.w, dr };
    const float O[4] = { o4.x, o4.y, o4.z, o4.w };
    float R[4];

#pragma unroll
    for (int i = 0; i < 4; i++) {
        const int idx = ((int)(O[i] * (1.0f / 45.0f))) & 7;
        const bool b0 = (idx & 1);
        const bool b1 = (idx & 2);
        const bool b2 = (idx & 4);

        // neighbor candidates: k = 0..7 -> (dy,dx) compass table
        // k0:C[i+2] k1:D[i+2] k2:D[i+1] k3:D[i]  k4:C[i] k5:U[i] k6:U[i+1] k7:U[i+2]
        const float a0  = b0 ? D[i + 2] : C[i + 2];   // k1 : k0
        const float a1  = b0 ? D[i]     : D[i + 1];   // k3 : k2
        const float s_l = b1 ? a1 : a0;               // nb[idx & 3]
        const float h0  = b0 ? U[i]     : C[i];       // k5 : k4
        const float h1  = b0 ? U[i + 2] : U[i + 1];   // k7 : k6
        const float s_h = b1 ? h1 : h0;               // nb[(idx & 3) | 4]

        const float fwd = b2 ? s_h : s_l;             // nb[idx]
        const float bwd = b2 ? s_l : s_h;             // nb[idx ^ 4]

        const float m   = C[i + 1];
        const float pos = (m - fwd) + sbias[idx];
        const float neg = (m - bwd) + sbias[idx ^ 4];
        R[i] = (fminf(pos, neg) > 0.0f) ? m : 0.0f;
    }

    __stcs(reinterpret_cast<float4*>(out + base),
           make_float4(R[0], R[1], R[2], R[3]));
}

extern "C" void kernel_launch(void* const* d_in, const int* in_sizes, int n_in,
                              void* d_out, int out_size)
{
    const float* mag  = (const float*)d_in[0];   // grad_magnitude [1,1,4096,4096]
    const float* ori  = (const float*)d_in[1];   // grad_orientation
    // d_in[2] = weight [8,1,3,3] -- fixed directional filters, collapsed analytically
    const float* bias = (const float*)d_in[3];   // bias [8]
    float* out = (float*)d_out;

    dim3 block(32, 8);                            // 128 x 8 pixels per block
    dim3 grid(IMG_W / 128, IMG_H / 8);            // (32, 512)
    nms_kernel<<<grid, block>>>(mag, ori, bias, out);
}

// round 9
// speedup vs baseline: 1.8219x; 1.1438x over previous
#include <cuda_runtime.h>
#include <cuda_bf16.h>
#include <stdint.h>

// Canny NMS, collapsed conv form — persistent (one-wave) grid-stride kernel.
// Body per 128x1-per-warp tile: zero scattered loads; 8 compass neighbors live
// in the register window {U,C,D} x {i,i+1,i+2}; fwd = nb[idx], bwd = nb[idx^4]
// via a shared 8-SEL predicate tree.
//   pos = m + bias[idx]   - fwd
//   neg = m + bias[idx^4] - bwd
//   out = (min(pos,neg) > 0) ? m : 0      (zero rows/cols = SAME padding)

#define IMG_H 4096
#define IMG_W 4096
#define FULLMASK 0xFFFFFFFFu
#define NTILE_X 32          // 4096 / 128
#define NTILES  16384       // 32 * 512
#define GRID    1184        // 148 SMs * 8 blocks (one wave)

__global__ __launch_bounds__(256, 8) void nms_kernel(
    const float* __restrict__ mag,
    const float* __restrict__ ori,
    const float* __restrict__ bias,
    float* __restrict__ out)
{
    __shared__ float sbias[8];
    const int lane = threadIdx.x;                   // 0..31
    const int wy   = threadIdx.y;                   // 0..7
    if (threadIdx.y == 0 && lane < 8) sbias[lane] = bias[lane];
    __syncthreads();

    for (int t = blockIdx.x; t < NTILES; t += GRID) {
        const int bx = t & (NTILE_X - 1);
        const int by = t >> 5;

        const int x = (bx * 32 + lane) * 4;
        const int y = by * 8 + wy;
        const int base = (y << 12) + x;

        const float4 z4 = make_float4(0.f, 0.f, 0.f, 0.f);

        // ---- vector loads: 3 mag rows + orientation (coalesced 512B/warp) ----
        const float4 c4 = *reinterpret_cast<const float4*>(mag + base);
        const float4 u4 = (y > 0)         ? *reinterpret_cast<const float4*>(mag + base - IMG_W) : z4;
        const float4 d4 = (y < IMG_H - 1) ? *reinterpret_cast<const float4*>(mag + base + IMG_W) : z4;
        const float4 o4 = __ldcs(reinterpret_cast<const float4*>(ori + base));

        // ---- extend rows to 6 columns via shuffles ----
        float cl = __shfl_up_sync(FULLMASK, c4.w, 1);
        float ul = __shfl_up_sync(FULLMASK, u4.w, 1);
        float dl = __shfl_up_sync(FULLMASK, d4.w, 1);
        float cr = __shfl_down_sync(FULLMASK, c4.x, 1);
        float ur = __shfl_down_sync(FULLMASK, u4.x, 1);
        float dr = __shfl_down_sync(FULLMASK, d4.x, 1);

        // warp-edge lanes: patch from gmem (2 active lanes)
        if (lane == 0) {
            const bool ok = (x > 0);
            cl = ok ? __ldg(mag + base - 1) : 0.f;
            ul = (ok && y > 0)         ? __ldg(mag + base - IMG_W - 1) : 0.f;
            dl = (ok && y < IMG_H - 1) ? __ldg(mag + base + IMG_W - 1) : 0.f;
        } else if (lane == 31) {
            const bool ok = (x + 4 < IMG_W);
            cr = ok ? __ldg(mag + base + 4) : 0.f;
            ur = (ok && y > 0)         ? __ldg(mag + base - IMG_W + 4) : 0.f;
            dr = (ok && y < IMG_H - 1) ? __ldg(mag + base + IMG_W + 4) : 0.f;
        }

        const float U[6] = { ul, u4.x, u4.y, u4.z, u4.w, ur };
        const float C[6] = { cl, c4.x, c4.y, c4.z, c4.w, cr };
        const float D[6] = { dl, d4.x, d4.y, d4.z, d4.w, dr };
        const float O[4] = { o4.x, o4.y, o4.z, o4.w };
        float R[4];

#pragma unroll
        for (int i = 0; i < 4; i++) {
            const int idx = ((int)(O[i] * (1.0f / 45.0f))) & 7;
            const bool b0 = (idx & 1);
            const bool b1 = (idx & 2);
            const bool b2 = (idx & 4);

            // k0:C[i+2] k1:D[i+2] k2:D[i+1] k3:D[i] k4:C[i] k5:U[i] k6:U[i+1] k7:U[i+2]
            const float a0  = b0 ? D[i + 2] : C[i + 2];
            const float a1  = b0 ? D[i]     : D[i + 1];
            const float s_l = b1 ? a1 : a0;               // nb[idx & 3]
            const float h0  = b0 ? U[i]     : C[i];
            const float h1  = b0 ? U[i + 2] : U[i + 1];
            const float s_h = b1 ? h1 : h0;               // nb[(idx & 3) | 4]

            const float fwd = b2 ? s_h : s_l;             // nb[idx]
            const float bwd = b2 ? s_l : s_h;             // nb[idx ^ 4]

            const float m   = C[i + 1];
            const float pos = (m - fwd) + sbias[idx];
            const float neg = (m - bwd) + sbias[idx ^ 4];
            R[i] = (fminf(pos, neg) > 0.0f) ? m : 0.0f;
        }

        __stcs(reinterpret_cast<float4*>(out + base),
               make_float4(R[0], R[1], R[2], R[3]));
    }
}

extern "C" void kernel_launch(void* const* d_in, const int* in_sizes, int n_in,
                              void* d_out, int out_size)
{
    const float* mag  = (const float*)d_in[0];   // grad_magnitude [1,1,4096,4096]
    const float* ori  = (const float*)d_in[1];   // grad_orientation
    // d_in[2] = weight [8,1,3,3] -- fixed directional filters, collapsed analytically
    const float* bias = (const float*)d_in[3];   // bias [8]
    float* out = (float*)d_out;

    dim3 block(32, 8);                            // 128 x 8 pixels per tile
    nms_kernel<<<GRID, block>>>(mag, ori, bias, out);
}